// round 16
// baseline (speedup 1.0000x reference)
#include <cuda_runtime.h>
#include <cuda_fp16.h>

#define T_STEPS 2048
#define BATCH   256
#define HID     64
#define EMBED   128

__device__ __forceinline__ float fast_tanh(float x) {
    float y;
    asm("tanh.approx.f32 %0, %1;" : "=f"(y) : "f"(x));
    return y;
}
__device__ __forceinline__ float fast_sigm(float x) {
    return fmaf(fast_tanh(0.5f * x), 0.5f, 0.5f);
}
__device__ __forceinline__ __half2 u2h2(unsigned int u) {
    return *reinterpret_cast<__half2*>(&u);
}

// K-SPLIT thread->gate map (512 threads, 16 warps):
//   warp w (0..15), lane l (0..31):
//     unit j  = w*4 + (l>>3)      (4 units per warp, 64 total)
//     type    = (l>>1) & 3        (0:i 1:f 2:g 3:o, PyTorch order)
//     kh      = l & 1             (K-half: kh*32 .. kh*32+31)
//   weight row gr = type*64 + j; each thread holds ONLY its K-half (16 half2
//   per matrix, 5 matrices = 80 regs) and issues 160 HFMA2/step.
// Tail: per-thread partial -> shfl_xor(p,1) combines K-halves (bias added
// after), nonlinearity, then gate exchange shfl_xor 2/4/6 delivers (f,g,o)
// to every lane; the (type==0, kh==0) lane commits c/h for unit j.
// Non-committing lanes compute bounded garbage; never stored.
//
// Diagonal pipeline: superstep s computes l0[t=s], l1[t=s-1], l2[t=s-2];
// one __syncthreads per superstep. 4 warps/SMSP -> tail chains of one warp
// hide under the dot work of the other three.

#define LSTM_TAIL(LYR, ACC0, ACC1, IN0, IN1, Cr0, Cr1, H0OUT, H1OUT)           \
    {                                                                          \
        float2 tf0_ = __half22float2(__hadd2(ACC0[0], ACC0[1]));               \
        float p0_ = tf0_.x + tf0_.y;                                           \
        float2 tf1_ = __half22float2(__hadd2(ACC1[0], ACC1[1]));               \
        float p1_ = tf1_.x + tf1_.y;                                           \
        float v0 = (IN0) + p0_ + __shfl_xor_sync(0xffffffffu, p0_, 1);         \
        float v1 = (IN1) + p1_ + __shfl_xor_sync(0xffffffffu, p1_, 1);         \
        if (type == 2) { v0 = fast_tanh(v0); v1 = fast_tanh(v1); }             \
        else           { v0 = fast_sigm(v0); v1 = fast_sigm(v1); }             \
        float f0 = __shfl_xor_sync(0xffffffffu, v0, 2);                        \
        float g0 = __shfl_xor_sync(0xffffffffu, v0, 4);                        \
        float o0 = __shfl_xor_sync(0xffffffffu, v0, 6);                        \
        float f1 = __shfl_xor_sync(0xffffffffu, v1, 2);                        \
        float g1 = __shfl_xor_sync(0xffffffffu, v1, 4);                        \
        float o1 = __shfl_xor_sync(0xffffffffu, v1, 6);                        \
        Cr0 = f0 * Cr0 + v0 * g0;                                              \
        Cr1 = f1 * Cr1 + v1 * g1;                                              \
        float h0_ = o0 * fast_tanh(Cr0);                                       \
        float h1_ = o1 * fast_tanh(Cr1);                                       \
        if (type == 0 && kh == 0) {                                            \
            hs[nxt][LYR][0][j] = __float2half_rn(h0_);                         \
            hs[nxt][LYR][1][j] = __float2half_rn(h1_);                         \
        }                                                                      \
        H0OUT = h0_; H1OUT = h1_;                                              \
    }

// One phase: 4 uint4 loads per row (this thread's K-half), 16 HFMA2 per dot.
// DOT(acc, wreg, m, hval): acc[(m)&1] to give two depth-8 chains.
#define PHASE2(PaROW0, PaROW1, WX, XACC0, XACC1, WY, YACC0, YACC1)             \
    {                                                                          \
        const uint4* Pa_ = (PaROW0);                                           \
        const uint4* Pb_ = (PaROW1);                                           \
        _Pragma("unroll")                                                      \
        for (int q = 0; q < 4; q++) {                                          \
            uint4 ha = Pa_[q], hb = Pb_[q];                                    \
            __half2 a0 = u2h2(ha.x), a1 = u2h2(ha.y),                          \
                    a2 = u2h2(ha.z), a3 = u2h2(ha.w);                          \
            __half2 e0 = u2h2(hb.x), e1 = u2h2(hb.y),                          \
                    e2 = u2h2(hb.z), e3 = u2h2(hb.w);                          \
            XACC0[0] = __hfma2(WX[4*q+0], a0, XACC0[0]);                       \
            XACC0[1] = __hfma2(WX[4*q+1], a1, XACC0[1]);                       \
            XACC0[0] = __hfma2(WX[4*q+2], a2, XACC0[0]);                       \
            XACC0[1] = __hfma2(WX[4*q+3], a3, XACC0[1]);                       \
            XACC1[0] = __hfma2(WX[4*q+0], e0, XACC1[0]);                       \
            XACC1[1] = __hfma2(WX[4*q+1], e1, XACC1[1]);                       \
            XACC1[0] = __hfma2(WX[4*q+2], e2, XACC1[0]);                       \
            XACC1[1] = __hfma2(WX[4*q+3], e3, XACC1[1]);                       \
            YACC0[0] = __hfma2(WY[4*q+0], a0, YACC0[0]);                       \
            YACC0[1] = __hfma2(WY[4*q+1], a1, YACC0[1]);                       \
            YACC0[0] = __hfma2(WY[4*q+2], a2, YACC0[0]);                       \
            YACC0[1] = __hfma2(WY[4*q+3], a3, YACC0[1]);                       \
            YACC1[0] = __hfma2(WY[4*q+0], e0, YACC1[0]);                       \
            YACC1[1] = __hfma2(WY[4*q+1], e1, YACC1[1]);                       \
            YACC1[0] = __hfma2(WY[4*q+2], e2, YACC1[0]);                       \
            YACC1[1] = __hfma2(WY[4*q+3], e3, YACC1[1]);                       \
        }                                                                      \
    }

#define PHASE1(PaROW0, PaROW1, WX, XACC0, XACC1)                               \
    {                                                                          \
        const uint4* Pa_ = (PaROW0);                                           \
        const uint4* Pb_ = (PaROW1);                                           \
        _Pragma("unroll")                                                      \
        for (int q = 0; q < 4; q++) {                                          \
            uint4 ha = Pa_[q], hb = Pb_[q];                                    \
            XACC0[0] = __hfma2(WX[4*q+0], u2h2(ha.x), XACC0[0]);               \
            XACC0[1] = __hfma2(WX[4*q+1], u2h2(ha.y), XACC0[1]);               \
            XACC0[0] = __hfma2(WX[4*q+2], u2h2(ha.z), XACC0[0]);               \
            XACC0[1] = __hfma2(WX[4*q+3], u2h2(ha.w), XACC0[1]);               \
            XACC1[0] = __hfma2(WX[4*q+0], u2h2(hb.x), XACC1[0]);               \
            XACC1[1] = __hfma2(WX[4*q+1], u2h2(hb.y), XACC1[1]);               \
            XACC1[0] = __hfma2(WX[4*q+2], u2h2(hb.z), XACC1[0]);               \
            XACC1[1] = __hfma2(WX[4*q+3], u2h2(hb.w), XACC1[1]);               \
        }                                                                      \
    }

__global__ void __launch_bounds__(512, 1) lstm_all(
    const float* __restrict__ x,
    const float* __restrict__ Wih0, const float* __restrict__ Whh0,
    const float* __restrict__ bih0, const float* __restrict__ bhh0,
    const float* __restrict__ Wih1, const float* __restrict__ Whh1,
    const float* __restrict__ bih1, const float* __restrict__ bhh1,
    const float* __restrict__ Wih2, const float* __restrict__ Whh2,
    const float* __restrict__ bih2, const float* __restrict__ bhh2,
    const float* __restrict__ fcW,  const float* __restrict__ fcb,
    float* __restrict__ out)
{
    __shared__ __align__(16) float  xs[2][T_STEPS];       // 16 KB
    __shared__ __align__(16) __half hs[2][3][2][HID];     // [parity][layer][row][j]
    __shared__ __align__(16) float  h2last[2][HID];

    const int tid = threadIdx.x;
    const int b0  = blockIdx.x * 2;

    {   // stage x rows (coalesced float4, 512 threads x 2)
        const float4* xr = (const float4*)(x + (size_t)b0 * T_STEPS);
        float4* xd = (float4*)xs;
        xd[tid]       = xr[tid];
        xd[tid + 512] = xr[tid + 512];
    }

    const int w = tid >> 5, l = tid & 31;
    const int j    = (w << 2) | (l >> 3);
    const int type = (l >> 1) & 3;
    const int kh   = l & 1;
    const int gr   = type * HID + j;
    const int kofs = kh * (HID / 2);      // 0 or 32

    const float wih0v = Wih0[gr];
    const float bias0 = bih0[gr] + bhh0[gr];
    const float bias1 = bih1[gr] + bhh1[gr];
    const float bias2 = bih2[gr] + bhh2[gr];

    // K-half weights as half2: 5 x 16 regs.
    __half2 w0r[16], w1i[16], w1r[16], w2i[16], w2r[16];
    {
        const float2* p0 = (const float2*)(Whh0 + gr * HID + kofs);
        const float2* p1 = (const float2*)(Wih1 + gr * HID + kofs);
        const float2* p2 = (const float2*)(Whh1 + gr * HID + kofs);
        const float2* p3 = (const float2*)(Wih2 + gr * HID + kofs);
        const float2* p4 = (const float2*)(Whh2 + gr * HID + kofs);
#pragma unroll
        for (int q = 0; q < 16; q++) {
            w0r[q] = __float22half2_rn(p0[q]);
            w1i[q] = __float22half2_rn(p1[q]);
            w1r[q] = __float22half2_rn(p2[q]);
            w2i[q] = __float22half2_rn(p3[q]);
            w2r[q] = __float22half2_rn(p4[q]);
        }
    }

    // Zero both parities of all layer states (bounded reads during fill).
    if (tid < 192) ((__half2*)hs)[tid] = __float2half2_rn(0.f);
    float c00 = 0.f, c01 = 0.f, c10 = 0.f, c11 = 0.f, c20 = 0.f, c21 = 0.f;
    __syncthreads();

    for (int s = 0; s < T_STEPS + 2; s++) {
        const int cur = s & 1, nxt = cur ^ 1;

        __half2 A0[2], A1[2], B0[2], B1[2], C0[2], C1[2];
#pragma unroll
        for (int i = 0; i < 2; i++) {
            A0[i] = __float2half2_rn(0.f); A1[i] = __float2half2_rn(0.f);
            B0[i] = __float2half2_rn(0.f); B1[i] = __float2half2_rn(0.f);
            C0[i] = __float2half2_rn(0.f); C1[i] = __float2half2_rn(0.f);
        }

        // Phase 1: h0[cur] -> l0 rec (A, w0r) + l1 input (B, w1i).
        PHASE2((const uint4*)&hs[cur][0][0][kofs],
               (const uint4*)&hs[cur][0][1][kofs],
               w0r, A0, A1, w1i, B0, B1)

        float hd0, hd1;
        if (s < T_STEPS) {        // tail l0, t = s
            LSTM_TAIL(0, A0, A1,
                      fmaf(wih0v, xs[0][s], bias0),
                      fmaf(wih0v, xs[1][s], bias0),
                      c00, c01, hd0, hd1)
        }

        // Phase 2: h1[cur] -> l1 rec (B, w1r) + l2 input (C, w2i).
        PHASE2((const uint4*)&hs[cur][1][0][kofs],
               (const uint4*)&hs[cur][1][1][kofs],
               w1r, B0, B1, w2i, C0, C1)

        if (s >= 1 && s <= T_STEPS) {   // tail l1, t = s-1
            LSTM_TAIL(1, B0, B1, bias1, bias1, c10, c11, hd0, hd1)
        }

        // Phase 3: h2[cur] -> l2 rec (C, w2r).
        PHASE1((const uint4*)&hs[cur][2][0][kofs],
               (const uint4*)&hs[cur][2][1][kofs],
               w2r, C0, C1)

        if (s >= 2) {                    // tail l2, t = s-2
            LSTM_TAIL(2, C0, C1, bias2, bias2, c20, c21, hd0, hd1)
            if (s == T_STEPS + 1 && type == 0 && kh == 0) {
                h2last[0][j] = hd0;
                h2last[1][j] = hd1;
            }
        }
        __syncthreads();
    }

    // Fused FC: out[b0+r][e] = h2last[r] . fcW[e] + fcb[e]  (first 256 threads)
    if (tid < 256) {
        const int r = tid >> 7, e = tid & 127;
        const float4* w4 = (const float4*)(fcW + e * HID);
        const float4* h4 = (const float4*)(h2last[r]);
        float acc = 0.f;
#pragma unroll
        for (int q = 0; q < 16; q++) {
            float4 a = w4[q], h = h4[q];
            acc = fmaf(a.x, h.x, acc);
            acc = fmaf(a.y, h.y, acc);
            acc = fmaf(a.z, h.z, acc);
            acc = fmaf(a.w, h.w, acc);
        }
        out[(size_t)(b0 + r) * EMBED + e] = acc + fcb[e];
    }
}

// ============================================================================
extern "C" void kernel_launch(void* const* d_in, const int* in_sizes, int n_in,
                              void* d_out, int out_size)
{
    const float* x    = (const float*)d_in[0];
    const float* Wih0 = (const float*)d_in[1];
    const float* Whh0 = (const float*)d_in[2];
    const float* bih0 = (const float*)d_in[3];
    const float* bhh0 = (const float*)d_in[4];
    const float* Wih1 = (const float*)d_in[5];
    const float* Whh1 = (const float*)d_in[6];
    const float* bih1 = (const float*)d_in[7];
    const float* bhh1 = (const float*)d_in[8];
    const float* Wih2 = (const float*)d_in[9];
    const float* Whh2 = (const float*)d_in[10];
    const float* bih2 = (const float*)d_in[11];
    const float* bhh2 = (const float*)d_in[12];
    const float* fcW  = (const float*)d_in[13];
    const float* fcb  = (const float*)d_in[14];

    lstm_all<<<BATCH / 2, 512>>>(x,
                                 Wih0, Whh0, bih0, bhh0,
                                 Wih1, Whh1, bih1, bhh1,
                                 Wih2, Whh2, bih2, bhh2,
                                 fcW, fcb, (float*)d_out);
}